// round 7
// baseline (speedup 1.0000x reference)
#include <cuda_runtime.h>
#include <cstring>

#define BB   8
#define CIN  8
#define COUT 16
#define HH   256
#define WW   256
#define HW   (HH * WW)          // 65536
#define NPIX (BB * HW)          // 524288
#define GROUPS_PER_IMG (HW / 4) // 16384 float4 pixel-groups per image
#define O_SPLIT 4
#define O_PER   (COUT / O_SPLIT) // 4 outputs per thread

__device__ __forceinline__ float ex2(float v) {
    float r;
    asm("ex2.approx.ftz.f32 %0, %1;" : "=f"(r) : "f"(v));
    return r;
}

// Packed f32x2 ops (Blackwell sm_103a)
__device__ __forceinline__ float2 add2(float2 a, float2 b) {
    unsigned long long ra, rb, rr;
    memcpy(&ra, &a, 8); memcpy(&rb, &b, 8);
    asm("add.rn.f32x2 %0, %1, %2;" : "=l"(rr) : "l"(ra), "l"(rb));
    float2 r; memcpy(&r, &rr, 8);
    return r;
}
__device__ __forceinline__ float2 fma2(float2 a, float2 b, float2 c) {
    unsigned long long ra, rb, rc, rr;
    memcpy(&ra, &a, 8); memcpy(&rb, &b, 8); memcpy(&rc, &c, 8);
    asm("fma.rn.f32x2 %0, %1, %2, %3;" : "=l"(rr) : "l"(ra), "l"(rb), "l"(rc));
    float2 r; memcpy(&r, &rr, 8);
    return r;
}

__global__ __launch_bounds__(128, 10) void rbf_hist_kernel(
    const float* __restrict__ x,
    const float* __restrict__ centers,
    const float* __restrict__ widths,
    float* __restrict__ out)
{
    // Exponent in log2 domain as FMA form: g = (A*x + B)*x + C
    //   A = -log2e/(2w^2), B = -2Ac, C = A c^2  (rel_err ~4e-7, verified R5/R6)
    // Stored j-major so the inner o-loop reads [j*COUT + o].
    __shared__ float4 s_ab[CIN * COUT];   // (A, A, B, B)
    __shared__ float2 s_c[CIN * COUT];    // (C, C)

    int tid = threadIdx.x;
    if (tid < COUT * CIN) {
        int o = tid / CIN, j = tid % CIN;
        float c = centers[tid];
        float w = widths[tid];
        float A = -1.44269504088896340736f / (2.0f * w * w);
        float Bv = -2.0f * A * c;
        float Cv = A * c * c;
        s_ab[j * COUT + o] = make_float4(A, A, Bv, Bv);
        s_c[j * COUT + o]  = make_float2(Cv, Cv);
    }
    __syncthreads();

    int idx = blockIdx.x * blockDim.x + tid;    // pixel-group id
    int b   = idx >> 14;
    int p4  = idx & (GROUPS_PER_IMG - 1);
    const float* xp = x + b * CIN * HW + p4 * 4;
    int obase = b * COUT * HW + p4 * 4;
    int o0  = blockIdx.y * O_PER;               // this block's output quarter

    // 8 packed accumulators (16 regs): [oo] x {A,B} halves of the 4 pixels
    float2 accA[O_PER], accB[O_PER];
    #pragma unroll
    for (int oo = 0; oo < O_PER; oo++) {
        accA[oo] = make_float2(0.f, 0.f);
        accB[oo] = make_float2(0.f, 0.f);
    }

    #pragma unroll
    for (int j = 0; j < CIN; j++) {             // x streamed: one float4 live
        float4 v = *reinterpret_cast<const float4*>(xp + j * HW);
        float2 xa = make_float2(v.x, v.y);
        float2 xb = make_float2(v.z, v.w);
        #pragma unroll
        for (int oo = 0; oo < O_PER; oo++) {
            int coef = j * COUT + o0 + oo;
            float4 ab = s_ab[coef];
            float2 A  = make_float2(ab.x, ab.y);
            float2 Bv = make_float2(ab.z, ab.w);
            float2 Cv = s_c[coef];
            float2 gA = fma2(fma2(A, xa, Bv), xa, Cv);
            float2 gB = fma2(fma2(A, xb, Bv), xb, Cv);
            accA[oo] = add2(accA[oo], make_float2(ex2(gA.x), ex2(gA.y)));
            accB[oo] = add2(accB[oo], make_float2(ex2(gB.x), ex2(gB.y)));
        }
    }

    #pragma unroll
    for (int oo = 0; oo < O_PER; oo++) {
        float4 r = make_float4(accA[oo].x, accA[oo].y, accB[oo].x, accB[oo].y);
        *reinterpret_cast<float4*>(out + obase + (o0 + oo) * HW) = r;
    }
}

extern "C" void kernel_launch(void* const* d_in, const int* in_sizes, int n_in,
                              void* d_out, int out_size)
{
    const float* x       = (const float*)d_in[0];
    const float* centers = (const float*)d_in[1];
    const float* widths  = (const float*)d_in[2];
    float* out           = (float*)d_out;

    const int threads = 128;
    const int groups  = NPIX / 4;                  // 131072 pixel-group threads
    dim3 grid(groups / threads, O_SPLIT);          // (1024, 4)
    rbf_hist_kernel<<<grid, threads>>>(x, centers, widths, out);
}

// round 8
// speedup vs baseline: 1.0882x; 1.0882x over previous
#include <cuda_runtime.h>
#include <cstring>

#define BB   8
#define CIN  8
#define COUT 16
#define HH   256
#define WW   256
#define HW   (HH * WW)          // 65536
#define NPIX (BB * HW)          // 524288
#define GROUPS_PER_IMG (HW / 4) // 16384 float4 pixel-groups per image
#define O_SPLIT 2
#define O_PER   (COUT / O_SPLIT) // 8 outputs per item
#define N_ITEMS (NPIX / 4 / 128 * O_SPLIT)  // 2048 virtual blocks of work
#define N_BLOCKS 1184                        // 148 SMs x 8 resident blocks

__device__ __forceinline__ float ex2(float v) {
    float r;
    asm("ex2.approx.ftz.f32 %0, %1;" : "=f"(r) : "f"(v));
    return r;
}

// Packed f32x2 ops (Blackwell sm_103a)
__device__ __forceinline__ float2 add2(float2 a, float2 b) {
    unsigned long long ra, rb, rr;
    memcpy(&ra, &a, 8); memcpy(&rb, &b, 8);
    asm("add.rn.f32x2 %0, %1, %2;" : "=l"(rr) : "l"(ra), "l"(rb));
    float2 r; memcpy(&r, &rr, 8);
    return r;
}
__device__ __forceinline__ float2 fma2(float2 a, float2 b, float2 c) {
    unsigned long long ra, rb, rc, rr;
    memcpy(&ra, &a, 8); memcpy(&rb, &b, 8); memcpy(&rc, &c, 8);
    asm("fma.rn.f32x2 %0, %1, %2, %3;" : "=l"(rr) : "l"(ra), "l"(rb), "l"(rc));
    float2 r; memcpy(&r, &rr, 8);
    return r;
}

__global__ __launch_bounds__(128, 8) void rbf_hist_kernel(
    const float* __restrict__ x,
    const float* __restrict__ centers,
    const float* __restrict__ widths,
    float* __restrict__ out)
{
    // Exponent in log2 domain as FMA form: g = (A*x + B)*x + C
    //   A = -log2e/(2w^2), B = -2Ac, C = A c^2  (rel_err ~4e-7, verified R5/R6)
    __shared__ float4 s_ab[COUT * CIN];   // (A, A, B, B)
    __shared__ float2 s_c[COUT * CIN];    // (C, C)

    int tid = threadIdx.x;
    if (tid < COUT * CIN) {
        float c = centers[tid];
        float w = widths[tid];
        float A = -1.44269504088896340736f / (2.0f * w * w);
        float Bv = -2.0f * A * c;
        float Cv = A * c * c;
        s_ab[tid] = make_float4(A, A, Bv, Bv);
        s_c[tid]  = make_float2(Cv, Cv);
    }
    __syncthreads();

    // Persistent: grid-stride over 2048 virtual work items in ONE launch wave.
    for (int item = blockIdx.x; item < N_ITEMS; item += N_BLOCKS) {
        int vbx  = item & 1023;             // virtual block x (pixel groups)
        int half = item >> 10;              // output half 0/1
        int idx  = vbx * 128 + tid;         // pixel-group id
        int b    = idx >> 14;
        int p4   = idx & (GROUPS_PER_IMG - 1);
        const float* xp = x + b * CIN * HW + p4 * 4;
        int obase = b * COUT * HW + p4 * 4;
        int o0    = half * O_PER;

        float2 xa[CIN], xb[CIN];
        #pragma unroll
        for (int j = 0; j < CIN; j++) {
            float4 v = *reinterpret_cast<const float4*>(xp + j * HW);
            xa[j] = make_float2(v.x, v.y);
            xb[j] = make_float2(v.z, v.w);
        }

        #pragma unroll
        for (int oo = 0; oo < O_PER; oo++) {
            int o = o0 + oo;
            float2 accA = make_float2(0.f, 0.f);
            float2 accB = make_float2(0.f, 0.f);
            #pragma unroll
            for (int j = 0; j < CIN; j++) {
                float4 ab = s_ab[o * CIN + j];
                float2 A  = make_float2(ab.x, ab.y);
                float2 Bv = make_float2(ab.z, ab.w);
                float2 Cv = s_c[o * CIN + j];
                float2 gA = fma2(fma2(A, xa[j], Bv), xa[j], Cv);
                float2 gB = fma2(fma2(A, xb[j], Bv), xb[j], Cv);
                accA = add2(accA, make_float2(ex2(gA.x), ex2(gA.y)));
                accB = add2(accB, make_float2(ex2(gB.x), ex2(gB.y)));
            }
            float4 r = make_float4(accA.x, accA.y, accB.x, accB.y);
            *reinterpret_cast<float4*>(out + obase + o * HW) = r;
        }
    }
}

extern "C" void kernel_launch(void* const* d_in, const int* in_sizes, int n_in,
                              void* d_out, int out_size)
{
    const float* x       = (const float*)d_in[0];
    const float* centers = (const float*)d_in[1];
    const float* widths  = (const float*)d_in[2];
    float* out           = (float*)d_out;

    rbf_hist_kernel<<<N_BLOCKS, 128>>>(x, centers, widths, out);
}

// round 9
// speedup vs baseline: 1.1065x; 1.0168x over previous
#include <cuda_runtime.h>
#include <cuda_fp16.h>
#include <cstring>

#define BB   8
#define CIN  8
#define COUT 16
#define HH   256
#define WW   256
#define HW   (HH * WW)          // 65536
#define NPIX (BB * HW)          // 524288
#define GROUPS_PER_IMG (HW / 4) // 16384 float4 pixel-groups per image
#define O_SPLIT 2
#define O_PER   (COUT / O_SPLIT) // 8 outputs per thread

// Packed f32x2 FMA (Blackwell sm_103a)
__device__ __forceinline__ float2 fma2(float2 a, float2 b, float2 c) {
    unsigned long long ra, rb, rc, rr;
    memcpy(&ra, &a, 8); memcpy(&rb, &b, 8); memcpy(&rc, &c, 8);
    asm("fma.rn.f32x2 %0, %1, %2, %3;" : "=l"(rr) : "l"(ra), "l"(rb), "l"(rc));
    float2 r; memcpy(&r, &rr, 8);
    return r;
}

// Packed half exp2: ONE MUFU op -> TWO exp2 results.
__device__ __forceinline__ __half2 h2ex2(__half2 v) {
    unsigned ri, ro;
    memcpy(&ri, &v, 4);
    asm("ex2.approx.f16x2 %0, %1;" : "=r"(ro) : "r"(ri));
    __half2 r; memcpy(&r, &ro, 4);
    return r;
}

__global__ __launch_bounds__(128) void rbf_hist_kernel(
    const float* __restrict__ x,
    const float* __restrict__ centers,
    const float* __restrict__ widths,
    float* __restrict__ out)
{
    // Exponent in log2 domain, FMA form: g = (A*x + B)*x + C  (f32 throughout)
    //   A = -log2e/(2w^2), B = -2Ac, C = A c^2
    __shared__ float4 s_ab[COUT * CIN];   // (A, A, B, B)
    __shared__ float2 s_c[COUT * CIN];    // (C, C)

    int tid = threadIdx.x;
    if (tid < COUT * CIN) {
        float c = centers[tid];
        float w = widths[tid];
        float A = -1.44269504088896340736f / (2.0f * w * w);
        float Bv = -2.0f * A * c;
        float Cv = A * c * c;
        s_ab[tid] = make_float4(A, A, Bv, Bv);
        s_c[tid]  = make_float2(Cv, Cv);
    }
    __syncthreads();

    int idx = blockIdx.x * blockDim.x + tid;    // pixel-group id
    int b   = idx >> 14;
    int p4  = idx & (GROUPS_PER_IMG - 1);
    const float* xp = x + b * CIN * HW + p4 * 4;
    int obase = b * COUT * HW + p4 * 4;
    int o0  = blockIdx.y * O_PER;

    float2 xa[CIN], xb[CIN];
    #pragma unroll
    for (int j = 0; j < CIN; j++) {
        float4 v = *reinterpret_cast<const float4*>(xp + j * HW);
        xa[j] = make_float2(v.x, v.y);
        xb[j] = make_float2(v.z, v.w);
    }

    #pragma unroll
    for (int oo = 0; oo < O_PER; oo++) {
        int o = o0 + oo;
        __half2 hA[CIN], hB[CIN];
        #pragma unroll
        for (int j = 0; j < CIN; j++) {
            float4 ab = s_ab[o * CIN + j];
            float2 A  = make_float2(ab.x, ab.y);
            float2 Bv = make_float2(ab.z, ab.w);
            float2 Cv = s_c[o * CIN + j];
            float2 gA = fma2(fma2(A, xa[j], Bv), xa[j], Cv);
            float2 gB = fma2(fma2(A, xb[j], Bv), xb[j], Cv);
            hA[j] = h2ex2(__floats2half2_rn(gA.x, gA.y));
            hB[j] = h2ex2(__floats2half2_rn(gB.x, gB.y));
        }
        // 3-level pairwise tree: bounds f16 rounding to 3 levels per element.
        __half2 sA = __hadd2(__hadd2(__hadd2(hA[0], hA[1]), __hadd2(hA[2], hA[3])),
                             __hadd2(__hadd2(hA[4], hA[5]), __hadd2(hA[6], hA[7])));
        __half2 sB = __hadd2(__hadd2(__hadd2(hB[0], hB[1]), __hadd2(hB[2], hB[3])),
                             __hadd2(__hadd2(hB[4], hB[5]), __hadd2(hB[6], hB[7])));
        float2 fA = __half22float2(sA);
        float2 fB = __half22float2(sB);
        float4 r = make_float4(fA.x, fA.y, fB.x, fB.y);
        *reinterpret_cast<float4*>(out + obase + o * HW) = r;
    }
}

extern "C" void kernel_launch(void* const* d_in, const int* in_sizes, int n_in,
                              void* d_out, int out_size)
{
    const float* x       = (const float*)d_in[0];
    const float* centers = (const float*)d_in[1];
    const float* widths  = (const float*)d_in[2];
    float* out           = (float*)d_out;

    const int threads = 128;
    const int groups  = NPIX / 4;                  // 131072 pixel-group threads
    dim3 grid(groups / threads, O_SPLIT);          // (1024, 2)
    rbf_hist_kernel<<<grid, threads>>>(x, centers, widths, out);
}